// round 5
// baseline (speedup 1.0000x reference)
#include <cuda_runtime.h>
#include <math_constants.h>

#define B_   16
#define N_   16384
#define M_   256
#define TPB  256
#define GPTS 128                       // points per block
#define NGRP 4                         // m-split groups of 64 threads
#define PADM 264                       // contacts padded (max scan = T+3 <= 258)
#define NBLK ((N_ / GPTS) * B_)        // 2048 blocks

// ---- packed f32x2 helpers (each op = 1 SASS inst, rounds per-lane like scalar) ----
#define MUL2(o,a,b)   asm("mul.rn.f32x2 %0, %1, %2;"     : "=l"(o) : "l"(a), "l"(b))
#define ADD2(o,a,b)   asm("add.rn.f32x2 %0, %1, %2;"     : "=l"(o) : "l"(a), "l"(b))
#define FMA2(o,a,b,c) asm("fma.rn.f32x2 %0, %1, %2, %3;" : "=l"(o) : "l"(a), "l"(b), "l"(c))
static __device__ __forceinline__ unsigned long long pk2(float lo, float hi) {
    unsigned long long r;
    asm("mov.b64 %0, {%1, %2};" : "=l"(r) : "f"(lo), "f"(hi));
    return r;
}
#define UNPK2(lo,hi,v) asm("mov.b64 {%0, %1}, %2;" : "=f"(lo), "=f"(hi) : "l"(v))

// -------- scratch (device globals; zero at load; last block re-zeroes) --------
__device__ float    g_cnt[B_ * M_];
__device__ float    g_sum[3 * B_ * M_];
__device__ float    g_sq [B_ * M_];
__device__ float    g_sl1;
__device__ unsigned g_done;

__global__ __launch_bounds__(TPB) void k_main(
    const float* __restrict__ data, const float* __restrict__ cp,
    const float* __restrict__ off,  const int* __restrict__ tc,
    const int* __restrict__ lab,    float* __restrict__ out)
{
    // contacts, duplicated for packed math: sA[m]={cx,cx | cy,cy}, sB[m]={cz,cz | cn,cn}
    __shared__ ulonglong2 sA[PADM], sB[PADM];
    __shared__ float s_bd[NGRP * GPTS];
    __shared__ int   s_bi[NGRP * GPTS];
    __shared__ float s_cnt[M_], s_sx[M_], s_sy[M_], s_sz[M_], s_sq[M_];
    __shared__ float s_red[TPB / 32];
    __shared__ unsigned s_last;

    const int b   = blockIdx.x;                  // batch in x -> interleaved CTA order
    const int pt  = blockIdx.y;                  // point tile
    const int t   = threadIdx.x;
    const int g   = t >> 6;                      // m-group 0..3
    const int pid = t & 63;
    const int T   = tc[b];
    const float INF = CUDART_INF_F;

    // fill contacts (pad m>=T with cn=+inf so d=+inf; never wins strict '<')
    for (int i = t; i < PADM; i += TPB) {
        float cx = 0.f, cy = 0.f, cz = 0.f, cn = INF;
        if (i < M_) {
            cx = cp[(b * M_ + i) * 3 + 0];
            cy = cp[(b * M_ + i) * 3 + 1];
            cz = cp[(b * M_ + i) * 3 + 2];
            if (i < T) cn = (cx * cx + cy * cy) + cz * cz;   // ref op order
        }
        sA[i] = make_ulonglong2(pk2(cx, cx), pk2(cy, cy));
        sB[i] = make_ulonglong2(pk2(cz, cz), pk2(cn, cn));
    }
    if (t < M_) { s_cnt[t] = 0.f; s_sx[t] = 0.f; s_sy[t] = 0.f; s_sz[t] = 0.f; s_sq[t] = 0.f; }
    __syncthreads();

    const int base = pt * GPTS;
    const int n0 = base + pid, n1 = n0 + 64;
    const float* dB = data + (size_t)b * 3 * N_;
    const float* oB = off  + (size_t)b * 3 * N_;

    const float px0 = dB[n0], py0 = dB[N_ + n0], pz0 = dB[2 * N_ + n0];
    const float px1 = dB[n1], py1 = dB[N_ + n1], pz1 = dB[2 * N_ + n1];
    const float pn0 = (px0 * px0 + py0 * py0) + pz0 * pz0;   // ref op order
    const float pn1 = (px1 * px1 + py1 * py1) + pz1 * pz1;

    const unsigned long long px2 = pk2(px0, px1), py2 = pk2(py0, py1);
    const unsigned long long pz2 = pk2(pz0, pz1), pn2 = pk2(pn0, pn1);
    const unsigned long long NEG2 = 0xC0000000C0000000ULL;   // {-2.f,-2.f}

    // this group's m-quarter; chunked scan of 4 m (may overrun into padding/next
    // group's range — harmless: strict '<' ascending-group combine keeps first index)
    const int mbeg = (g * T) >> 2;
    const int mend = ((g + 1) * T) >> 2;

    float bd0 = INF, bd1 = INF;
    int   cb0 = -1,  cb1 = -1;

    for (int mc = mbeg; mc < mend; mc += 4) {
        float cm0, cm1;
        #pragma unroll
        for (int j = 0; j < 4; j++) {
            ulonglong2 a = sA[mc + j];           // LDS.128 broadcast
            ulonglong2 bb = sB[mc + j];
            unsigned long long t1, t2, dot, s, d2;
            MUL2(t1, px2, a.x);
            FMA2(t2, py2, a.y, t1);
            FMA2(dot, pz2, bb.x, t2);            // fma chain: ref rounding
            ADD2(s, pn2, bb.y);                  // pn + cn
            FMA2(d2, NEG2, dot, s);              // (pn+cn) - 2*dot (2*dot exact)
            float d0, d1; UNPK2(d0, d1, d2);
            if (j == 0) { cm0 = d0; cm1 = d1; }
            else        { cm0 = fminf(cm0, d0); cm1 = fminf(cm1, d1); }
        }
        if (cm0 < bd0) { bd0 = cm0; cb0 = mc; }  // strict '<': earliest chunk wins
        if (cm1 < bd1) { bd1 = cm1; cb1 = mc; }
    }

    // rescan winning chunk DESCENDING, overwrite on '==' -> first index in chunk.
    // scalar recompute rounds bit-identically to the packed lanes.
    const float* vA = (const float*)sA;
    const float* vB = (const float*)sB;
    int bi0 = 0, bi1 = 0;
    if (cb0 >= 0) {
        #pragma unroll
        for (int j = 3; j >= 0; j--) {
            int m = cb0 + j;
            float cx = vA[m * 4], cy = vA[m * 4 + 2], cz = vB[m * 4], cn = vB[m * 4 + 2];
            float dot = fmaf(pz0, cz, fmaf(py0, cy, px0 * cx));
            float d   = fmaf(-2.0f, dot, pn0 + cn);
            if (d == bd0) bi0 = m;
        }
    }
    if (cb1 >= 0) {
        #pragma unroll
        for (int j = 3; j >= 0; j--) {
            int m = cb1 + j;
            float cx = vA[m * 4], cy = vA[m * 4 + 2], cz = vB[m * 4], cn = vB[m * 4 + 2];
            float dot = fmaf(pz1, cz, fmaf(py1, cy, px1 * cx));
            float d   = fmaf(-2.0f, dot, pn1 + cn);
            if (d == bd1) bi1 = m;
        }
    }
    s_bd[g * GPTS + pid]      = (cb0 >= 0) ? bd0 : INF;
    s_bi[g * GPTS + pid]      = bi0;
    s_bd[g * GPTS + 64 + pid] = (cb1 >= 0) ? bd1 : INF;
    s_bi[g * GPTS + 64 + pid] = bi1;
    __syncthreads();

    // ---- per-point epilogue: threads 0..127 each own one point ----
    const bool has = (T > 0);
    float ls = 0.f;
    if (t < GPTS) {
        float bd = s_bd[t];
        int   bi = s_bi[t];
        #pragma unroll
        for (int gg = 1; gg < NGRP; gg++) {      // ascending, strict '<'
            float v = s_bd[gg * GPTS + t];
            if (v < bd) { bd = v; bi = s_bi[gg * GPTS + t]; }
        }
        const int n = base + t;
        float px = dB[n], py = dB[N_ + n], pz = dB[2 * N_ + n];   // L1-hot
        float gx = 0.f, gy = 0.f, gz = 0.f;
        if (has) {
            gx = vA[bi * 4] - px; gy = vA[bi * 4 + 2] - py; gz = vB[bi * 4] - pz;
        }
        float* outB = out + (size_t)b * 3 * N_;
        outB[n] = gx; outB[N_ + n] = gy; outB[2 * N_ + n] = gz;

        float ox = oB[n], oy = oB[N_ + n], oz = oB[2 * N_ + n];
        if (lab[b] == 1) {
            float d, a;
            d = gx - ox; a = fabsf(d); ls += (a < 1.f) ? 0.5f * d * d : a - 0.5f;
            d = gy - oy; a = fabsf(d); ls += (a < 1.f) ? 0.5f * d * d : a - 0.5f;
            d = gz - oz; a = fabsf(d); ls += (a < 1.f) ? 0.5f * d * d : a - 0.5f;
        }
        if (has) {
            float ex = px + ox, ey = py + oy, ez = pz + oz;
            atomicAdd(&s_cnt[bi], 1.f);
            atomicAdd(&s_sx[bi], ex); atomicAdd(&s_sy[bi], ey); atomicAdd(&s_sz[bi], ez);
            atomicAdd(&s_sq[bi], (ex * ex + ey * ey) + ez * ez);
        }
    }

    // smooth-L1 block reduce -> one global atomic per block
    #pragma unroll
    for (int o = 16; o > 0; o >>= 1) ls += __shfl_down_sync(0xffffffffu, ls, o);
    if ((t & 31) == 0) s_red[t >> 5] = ls;
    __syncthreads();
    if (t == 0) {
        float s = 0.f;
        #pragma unroll
        for (int w = 0; w < TPB / 32; w++) s += s_red[w];
        if (s != 0.f) atomicAdd(&g_sl1, s);
    }

    // flush segment stats (all 256 threads, one contact each)
    if (has) {
        float c = s_cnt[t];
        if (c != 0.f) {
            int idx = b * M_ + t;
            atomicAdd(&g_cnt[idx], c);
            atomicAdd(&g_sum[0 * B_ * M_ + idx], s_sx[t]);
            atomicAdd(&g_sum[1 * B_ * M_ + idx], s_sy[t]);
            atomicAdd(&g_sum[2 * B_ * M_ + idx], s_sz[t]);
            atomicAdd(&g_sq[idx], s_sq[t]);
        }
    }

    // ---- last-block finalize ----
    __threadfence();
    if (t == 0) s_last = (atomicAdd(&g_done, 1u) == (unsigned)(NBLK - 1));
    __syncthreads();
    if (!s_last) return;

    __shared__ int s_tc[B_];
    if (t < B_) s_tc[t] = tc[t];
    __syncthreads();

    float acc = 0.f;
    #pragma unroll
    for (int idx = t; idx < B_ * M_; idx += TPB) {
        int bb = idx >> 8;
        float c  = __ldcg(&g_cnt[idx]);
        float sx = __ldcg(&g_sum[0 * B_ * M_ + idx]);
        float sy = __ldcg(&g_sum[1 * B_ * M_ + idx]);
        float sz = __ldcg(&g_sum[2 * B_ * M_ + idx]);
        float sq = __ldcg(&g_sq[idx]);
        if (s_tc[bb] > 0 && c > 0.f) {
            float vs = sq - ((sx * sx + sy * sy) + sz * sz) / c;
            acc += vs / c;
        }
        g_cnt[idx] = 0.f; g_sq[idx] = 0.f;      // re-zero for next replay
        g_sum[0 * B_ * M_ + idx] = 0.f;
        g_sum[1 * B_ * M_ + idx] = 0.f;
        g_sum[2 * B_ * M_ + idx] = 0.f;
    }
    #pragma unroll
    for (int o = 16; o > 0; o >>= 1) acc += __shfl_down_sync(0xffffffffu, acc, o);
    if ((t & 31) == 0) s_red[t >> 5] = acc;

    float nvalid = 0.f, nsel = 0.f;
    if (t < 32) {
        int v = (t < B_) ? s_tc[t] : 0;
        int l = (t < B_) ? lab[t] : 0;
        unsigned mv = __ballot_sync(0xffffffffu, v > 0);
        unsigned ml = __ballot_sync(0xffffffffu, l == 1);
        nvalid = (float)__popc(mv);
        nsel   = (float)__popc(ml);
    }
    __syncthreads();

    if (t == 0) {
        float vs = 0.f;
        #pragma unroll
        for (int w = 0; w < TPB / 32; w++) vs += s_red[w];
        nsel *= 3.0f * (float)N_;
        float sl1 = __ldcg(&g_sl1);
        float offset_loss = (nsel > 0.f) ? sl1 / fmaxf(nsel, 1.0f) : 0.f;
        float var_loss    = vs / (nvalid + 1e-16f);
        out[(size_t)B_ * 3 * N_] = offset_loss * 10.0f + var_loss * 2.0f;
        g_sl1 = 0.f;
        g_done = 0u;
    }
}

extern "C" void kernel_launch(void* const* d_in, const int* in_sizes, int n_in,
                              void* d_out, int out_size) {
    const float* data = (const float*)d_in[0];
    const float* cp   = (const float*)d_in[1];
    const float* off  = (const float*)d_in[2];
    const int*   tc   = (const int*)d_in[3];
    const int*   lab  = (const int*)d_in[4];
    float* out = (float*)d_out;

    dim3 grid(B_, N_ / GPTS);               // batch in x: interleaved CTA order
    k_main<<<grid, TPB>>>(data, cp, off, tc, lab, out);
}

// round 6
// speedup vs baseline: 1.0516x; 1.0516x over previous
#include <cuda_runtime.h>
#include <math_constants.h>

#define B_   16
#define N_   16384
#define M_   256
#define TPB  128
#define GPTS 128                       // points per block
#define HALF 64                        // threads per m-half
#define PADM 264                       // contacts padded: overscan <= T+6 <= 261
#define NBLK ((N_ / GPTS) * B_)        // 2048 blocks

// -------- scratch (device globals; zero at load; last block re-zeroes) --------
__device__ float    g_cnt[B_ * M_];
__device__ float    g_sum[3 * B_ * M_];
__device__ float    g_sq [B_ * M_];
__device__ float    g_sl1;
__device__ unsigned g_done;
__device__ int      g_order[B_];

// tiny LPT pre-pass: rank batches by descending T (stable)
__global__ void k_sort(const int* __restrict__ tc) {
    int i = threadIdx.x;
    if (i < B_) {
        int Ti = tc[i], r = 0;
        #pragma unroll
        for (int j = 0; j < B_; j++) {
            int Tj = tc[j];
            if (Tj > Ti || (Tj == Ti && j < i)) r++;
        }
        g_order[r] = i;
    }
}

__global__ __launch_bounds__(TPB) void k_main(
    const float* __restrict__ data, const float* __restrict__ cp,
    const float* __restrict__ off,  const int* __restrict__ tc,
    const int* __restrict__ lab,    float* __restrict__ out)
{
    __shared__ float4 sc[PADM];                        // {cx,cy,cz,cn|inf}
    __shared__ float s_cnt[M_], s_sx[M_], s_sy[M_], s_sz[M_], s_sq[M_];
    __shared__ float s_bdH[2][GPTS];
    __shared__ int   s_biH[2][GPTS];
    __shared__ float s_red[TPB / 32];
    __shared__ unsigned s_last;

    const int b    = g_order[blockIdx.x];              // LPT: long batches first
    const int pt   = blockIdx.y;
    const int t    = threadIdx.x;
    const int half = t >> 6;                           // m-half 0/1
    const int pid  = t & (HALF - 1);
    const int T    = tc[b];
    const float INF = CUDART_INF_F;

    // fill contacts; pad m >= T with cn=+inf (never wins strict '<')
    for (int i = t; i < PADM; i += TPB) {
        float cx = 0.f, cy = 0.f, cz = 0.f, cn = INF;
        if (i < M_) {
            cx = cp[(b * M_ + i) * 3 + 0];
            cy = cp[(b * M_ + i) * 3 + 1];
            cz = cp[(b * M_ + i) * 3 + 2];
            if (i < T) cn = (cx * cx + cy * cy) + cz * cz;   // ref op order
        }
        sc[i] = make_float4(cx, cy, cz, cn);
    }
    for (int i = t; i < M_; i += TPB) {
        s_cnt[i] = 0.f; s_sx[i] = 0.f; s_sy[i] = 0.f; s_sz[i] = 0.f; s_sq[i] = 0.f;
    }
    __syncthreads();

    const int base = pt * GPTS;
    const int n0 = base + pid, n1 = n0 + HALF;         // this thread's 2 points
    const float* dB = data + (size_t)b * 3 * N_;
    const float* oB = off  + (size_t)b * 3 * N_;

    const float px0 = dB[n0], py0 = dB[N_ + n0], pz0 = dB[2 * N_ + n0];
    const float px1 = dB[n1], py1 = dB[N_ + n1], pz1 = dB[2 * N_ + n1];
    const float pn0 = (px0 * px0 + py0 * py0) + pz0 * pz0;   // ref op order
    const float pn1 = (px1 * px1 + py1 * py1) + pz1 * pz1;

    // m-range for this half; overscan into [mend, mend+7) is safe:
    //  - half0's overlap indices are scanned after its own range (larger m),
    //    and half1 sees the same values, so strict-'<' ascending combine
    //    preserves exact first-index argmin
    //  - half1's overscan hits +inf padding
    const int mh   = T >> 1;
    const int mbeg = half ? mh : 0;
    const int mend = half ? T  : mh;

    int   bi0 = 0, bi1 = 0;
    float bd0 = INF, bd1 = INF;
    for (int m = mbeg; m < mend; m += 8) {
        #pragma unroll
        for (int j = 0; j < 8; j++) {
            float4 c = sc[m + j];                       // LDS.128 broadcast
            float dot0 = fmaf(pz0, c.z, fmaf(py0, c.y, px0 * c.x));
            float d0   = fmaf(-2.0f, dot0, pn0 + c.w);  // (pn+cn)-2*dot, 2*dot exact
            if (d0 < bd0) { bd0 = d0; bi0 = m + j; }
            float dot1 = fmaf(pz1, c.z, fmaf(py1, c.y, px1 * c.x));
            float d1   = fmaf(-2.0f, dot1, pn1 + c.w);
            if (d1 < bd1) { bd1 = d1; bi1 = m + j; }
        }
    }
    s_bdH[half][pid]        = bd0; s_biH[half][pid]        = bi0;
    s_bdH[half][HALF + pid] = bd1; s_biH[half][HALF + pid] = bi1;
    __syncthreads();

    // ---- per-point epilogue: each thread owns one point ----
    const bool has = (T > 0);
    float ls = 0.f;
    {
        float bd = s_bdH[0][t];
        int   bi = s_biH[0][t];
        float v  = s_bdH[1][t];
        if (v < bd) { bd = v; bi = s_biH[1][t]; }       // strict '<': first index

        const int n = base + t;
        float px = dB[n], py = dB[N_ + n], pz = dB[2 * N_ + n];   // L1-hot reload
        float gx = 0.f, gy = 0.f, gz = 0.f;
        if (has) {
            float4 c = sc[bi];
            gx = c.x - px; gy = c.y - py; gz = c.z - pz;
        }
        float* outB = out + (size_t)b * 3 * N_;
        outB[n] = gx; outB[N_ + n] = gy; outB[2 * N_ + n] = gz;

        float ox = oB[n], oy = oB[N_ + n], oz = oB[2 * N_ + n];
        if (lab[b] == 1) {
            float d, a;
            d = gx - ox; a = fabsf(d); ls += (a < 1.f) ? 0.5f * d * d : a - 0.5f;
            d = gy - oy; a = fabsf(d); ls += (a < 1.f) ? 0.5f * d * d : a - 0.5f;
            d = gz - oz; a = fabsf(d); ls += (a < 1.f) ? 0.5f * d * d : a - 0.5f;
        }
        if (has) {
            float ex = px + ox, ey = py + oy, ez = pz + oz;
            atomicAdd(&s_cnt[bi], 1.f);
            atomicAdd(&s_sx[bi], ex); atomicAdd(&s_sy[bi], ey); atomicAdd(&s_sz[bi], ez);
            atomicAdd(&s_sq[bi], (ex * ex + ey * ey) + ez * ez);
        }
    }

    // smooth-L1 block reduce -> one global atomic per block
    #pragma unroll
    for (int o = 16; o > 0; o >>= 1) ls += __shfl_down_sync(0xffffffffu, ls, o);
    if ((t & 31) == 0) s_red[t >> 5] = ls;
    __syncthreads();
    if (t == 0) {
        float s = 0.f;
        #pragma unroll
        for (int w = 0; w < TPB / 32; w++) s += s_red[w];
        if (s != 0.f) atomicAdd(&g_sl1, s);
    }

    // flush segment stats (128 threads cover 256 contacts)
    if (has) {
        #pragma unroll
        for (int i = t; i < M_; i += TPB) {
            float c = s_cnt[i];
            if (c != 0.f) {
                int idx = b * M_ + i;
                atomicAdd(&g_cnt[idx], c);
                atomicAdd(&g_sum[0 * B_ * M_ + idx], s_sx[i]);
                atomicAdd(&g_sum[1 * B_ * M_ + idx], s_sy[i]);
                atomicAdd(&g_sum[2 * B_ * M_ + idx], s_sz[i]);
                atomicAdd(&g_sq[idx], s_sq[i]);
            }
        }
    }

    // ---- last-block finalize ----
    __threadfence();
    if (t == 0) s_last = (atomicAdd(&g_done, 1u) == (unsigned)(NBLK - 1));
    __syncthreads();
    if (!s_last) return;

    __shared__ int s_tc[B_];
    if (t < B_) s_tc[t] = tc[t];
    __syncthreads();

    float acc = 0.f;
    #pragma unroll
    for (int idx = t; idx < B_ * M_; idx += TPB) {
        int bb = idx >> 8;                              // M_ == 256
        float c  = __ldcg(&g_cnt[idx]);
        float sx = __ldcg(&g_sum[0 * B_ * M_ + idx]);
        float sy = __ldcg(&g_sum[1 * B_ * M_ + idx]);
        float sz = __ldcg(&g_sum[2 * B_ * M_ + idx]);
        float sq = __ldcg(&g_sq[idx]);
        if (s_tc[bb] > 0 && c > 0.f) {
            float vs = sq - ((sx * sx + sy * sy) + sz * sz) / c;
            acc += vs / c;
        }
        g_cnt[idx] = 0.f; g_sq[idx] = 0.f;              // re-zero for next replay
        g_sum[0 * B_ * M_ + idx] = 0.f;
        g_sum[1 * B_ * M_ + idx] = 0.f;
        g_sum[2 * B_ * M_ + idx] = 0.f;
    }
    #pragma unroll
    for (int o = 16; o > 0; o >>= 1) acc += __shfl_down_sync(0xffffffffu, acc, o);
    if ((t & 31) == 0) s_red[t >> 5] = acc;

    float nvalid = 0.f, nsel = 0.f;
    if (t < 32) {
        int v = (t < B_) ? s_tc[t] : 0;
        int l = (t < B_) ? lab[t] : 0;
        unsigned mv = __ballot_sync(0xffffffffu, v > 0);
        unsigned ml = __ballot_sync(0xffffffffu, l == 1);
        nvalid = (float)__popc(mv);
        nsel   = (float)__popc(ml);
    }
    __syncthreads();

    if (t == 0) {
        float vs = 0.f;
        #pragma unroll
        for (int w = 0; w < TPB / 32; w++) vs += s_red[w];
        nsel *= 3.0f * (float)N_;
        float sl1 = __ldcg(&g_sl1);
        float offset_loss = (nsel > 0.f) ? sl1 / fmaxf(nsel, 1.0f) : 0.f;
        float var_loss    = vs / (nvalid + 1e-16f);
        out[(size_t)B_ * 3 * N_] = offset_loss * 10.0f + var_loss * 2.0f;
        g_sl1 = 0.f;
        g_done = 0u;
    }
}

extern "C" void kernel_launch(void* const* d_in, const int* in_sizes, int n_in,
                              void* d_out, int out_size) {
    const float* data = (const float*)d_in[0];
    const float* cp   = (const float*)d_in[1];
    const float* off  = (const float*)d_in[2];
    const int*   tc   = (const int*)d_in[3];
    const int*   lab  = (const int*)d_in[4];
    float* out = (float*)d_out;

    k_sort<<<1, 32>>>(tc);
    dim3 grid(B_, N_ / GPTS);        // x = LPT rank (fastest-varying in CTA order)
    k_main<<<grid, TPB>>>(data, cp, off, tc, lab, out);
}